// round 4
// baseline (speedup 1.0000x reference)
#include <cuda_runtime.h>
#include <cuda_bf16.h>

#define SLAB 32768          // 64*512 floats per time slab
#define HS 516              // padded stride (conflict-free LDS.128)

__device__ unsigned int g_flag[128];   // per-(group,utile) step counters

__device__ __forceinline__ void fma2(unsigned long long& d, unsigned long long a, unsigned long long b) {
    asm("fma.rn.f32x2 %0, %1, %2, %0;" : "+l"(d) : "l"(a), "l"(b));
}
__device__ __forceinline__ void add2(unsigned long long& d, unsigned long long a, unsigned long long b) {
    asm("add.rn.f32x2 %0, %1, %2;" : "=l"(d) : "l"(a), "l"(b));
}
__device__ __forceinline__ float2 u2f(unsigned long long v) {
    float2 r; asm("mov.b64 {%0, %1}, %2;" : "=f"(r.x), "=f"(r.y) : "l"(v)); return r;
}

// ---------------- Phase 1: out[t][b][u] = (x @ T)  ----------------
__global__ void __launch_bounds__(128) p1(const float* __restrict__ X,
                                          const float* __restrict__ T,
                                          float* __restrict__ out) {
    __shared__ float As[64 * 20];
    __shared__ float Ts[32 * 20];
    const int tid = threadIdx.x;
    if (blockIdx.x == 0 && blockIdx.y == 0 && tid < 128) g_flag[tid] = 0u;

    const int rowBase = blockIdx.x * 64;
    const int n0 = blockIdx.y * 32;
    const int mq = tid >> 3;
    const int nq = tid & 7;

    unsigned long long acc[4][4];
#pragma unroll
    for (int i = 0; i < 4; ++i)
#pragma unroll
        for (int j = 0; j < 4; ++j) acc[i][j] = 0ull;

    for (int kb = 0; kb < 256; kb += 16) {
#pragma unroll
        for (int i2 = 0; i2 < 2; ++i2) {
            int q = tid + i2 * 128;
            int m = q >> 2, kq = (q & 3) * 4;
            *(float4*)&As[m * 20 + kq] = *(const float4*)&X[(rowBase + m) * 256 + kb + kq];
        }
        {
            int k = tid >> 3, n4 = (tid & 7) * 4;
            float4 v = *(const float4*)&T[(kb + k) * 512 + n0 + n4];
            Ts[(n4 + 0) * 20 + k] = v.x;
            Ts[(n4 + 1) * 20 + k] = v.y;
            Ts[(n4 + 2) * 20 + k] = v.z;
            Ts[(n4 + 3) * 20 + k] = v.w;
        }
        __syncthreads();
#pragma unroll
        for (int k = 0; k < 16; k += 4) {
            ulonglong2 a0 = *(const ulonglong2*)&As[(mq) * 20 + k];
            ulonglong2 a1 = *(const ulonglong2*)&As[(mq + 16) * 20 + k];
            ulonglong2 a2 = *(const ulonglong2*)&As[(mq + 32) * 20 + k];
            ulonglong2 a3 = *(const ulonglong2*)&As[(mq + 48) * 20 + k];
            ulonglong2 b0 = *(const ulonglong2*)&Ts[(nq) * 20 + k];
            ulonglong2 b1 = *(const ulonglong2*)&Ts[(nq + 8) * 20 + k];
            ulonglong2 b2 = *(const ulonglong2*)&Ts[(nq + 16) * 20 + k];
            ulonglong2 b3 = *(const ulonglong2*)&Ts[(nq + 24) * 20 + k];
            fma2(acc[0][0], a0.x, b0.x); fma2(acc[0][0], a0.y, b0.y);
            fma2(acc[0][1], a0.x, b1.x); fma2(acc[0][1], a0.y, b1.y);
            fma2(acc[0][2], a0.x, b2.x); fma2(acc[0][2], a0.y, b2.y);
            fma2(acc[0][3], a0.x, b3.x); fma2(acc[0][3], a0.y, b3.y);
            fma2(acc[1][0], a1.x, b0.x); fma2(acc[1][0], a1.y, b0.y);
            fma2(acc[1][1], a1.x, b1.x); fma2(acc[1][1], a1.y, b1.y);
            fma2(acc[1][2], a1.x, b2.x); fma2(acc[1][2], a1.y, b2.y);
            fma2(acc[1][3], a1.x, b3.x); fma2(acc[1][3], a1.y, b3.y);
            fma2(acc[2][0], a2.x, b0.x); fma2(acc[2][0], a2.y, b0.y);
            fma2(acc[2][1], a2.x, b1.x); fma2(acc[2][1], a2.y, b1.y);
            fma2(acc[2][2], a2.x, b2.x); fma2(acc[2][2], a2.y, b2.y);
            fma2(acc[2][3], a2.x, b3.x); fma2(acc[2][3], a2.y, b3.y);
            fma2(acc[3][0], a3.x, b0.x); fma2(acc[3][0], a3.y, b0.y);
            fma2(acc[3][1], a3.x, b1.x); fma2(acc[3][1], a3.y, b1.y);
            fma2(acc[3][2], a3.x, b2.x); fma2(acc[3][2], a3.y, b2.y);
            fma2(acc[3][3], a3.x, b3.x); fma2(acc[3][3], a3.y, b3.y);
        }
        __syncthreads();
    }
#pragma unroll
    for (int i = 0; i < 4; ++i) {
        int r = rowBase + mq + 16 * i;
        int tt = r & 511, bb = r >> 9;
        float* p = out + tt * SLAB + bb * 512 + n0 + nq;
#pragma unroll
        for (int j = 0; j < 4; ++j) {
            float2 v = u2f(acc[i][j]);
            p[8 * j] = v.x + v.y;
        }
    }
}

// ---------------- Phase 2: recurrence, persistent 128 blocks ----------------
// grid (32,4): bx = utile (16 cols), g = batch group (16 rows). 256 thr = 8 warps.
// Warp w owns k-chunk [64w,64w+64): it polls only its 4 producer utiles' flags,
// loads only its own 4KB h-slice (warp-private smem), computes, then block-wide
// reduce over the 8 k-partials. Flags are per-block words (no atomic serialize).
__global__ void __launch_bounds__(256) p2(float* __restrict__ out,
                                          const float* __restrict__ B,
                                          const float* __restrict__ bias,
                                          const float* __restrict__ h0) {
    extern __shared__ float sm[];
    float* Bs = sm;                                          // 16 x HS
    float* hs = sm + 16 * HS;                                // 16 x HS (warp-private k-slabs)
    unsigned long long* red = (unsigned long long*)(sm + 32 * HS);  // 8 x 264

    const int tid = threadIdx.x;
    const int w = tid >> 5, lane = tid & 31;
    const int rq = lane & 7, cq = lane >> 3;
    const int g = blockIdx.y, bx = blockIdx.x;
    const int n0 = bx * 16, rowBase = g * 16;
    const int kBase = w * 64;
    const int orow = tid >> 4, ocol = tid & 15;
    const float bia = bias[n0 + ocol];
    const int myflag = g * 32 + bx;

    // one-time B slab (transposed): Bs[c][k] = B[k][n0+c]
    for (int idx = tid; idx < 16 * 512; idx += 256) {
        int k = idx >> 4, c = idx & 15;
        Bs[c * HS + k] = B[k * 512 + n0 + c];
    }
    __syncthreads();

    for (int t = 0; t < 512; ++t) {
        // prefetch xT term (hidden under compute)
        float xv = __ldcg(out + (size_t)t * SLAB + (rowBase + orow) * 512 + n0 + ocol);

        if (t > 0) {
            // wait only for this warp's 4 producer utiles (parallel poll, 4 lanes)
            bool ready = lane >= 4;
            const unsigned int* fp = &g_flag[g * 32 + 4 * w + lane];
            while (!__all_sync(0xffffffffu, ready)) {
                if (!ready) {
                    unsigned int v;
                    asm volatile("ld.global.cg.u32 %0, [%1];" : "=r"(v) : "l"(fp));
                    ready = (v >= (unsigned int)t);
                }
            }
            __threadfence();  // acquire: order h loads after flag observation
            // load this warp's h slice: 16 rows x 64 cols
            const float* hsrc = out + (size_t)(t - 1) * SLAB + rowBase * 512 + kBase;
#pragma unroll
            for (int i = 0; i < 8; ++i) {
                int u = lane + 32 * i;
                int r = u >> 4, c4 = (u & 15) * 4;
                float4 v = __ldcg((const float4*)(hsrc + r * 512 + c4));
                *(float4*)&hs[r * HS + kBase + c4] = v;
            }
        } else {
#pragma unroll
            for (int i = 0; i < 8; ++i) {
                int u = lane + 32 * i;
                int r = u >> 4, c4 = (u & 15) * 4;
                *(float4*)&hs[r * HS + kBase + c4] = *(const float4*)(h0 + kBase + c4);
            }
        }
        __syncwarp();

        unsigned long long a00 = 0, a01 = 0, a02 = 0, a03 = 0;
        unsigned long long a10 = 0, a11 = 0, a12 = 0, a13 = 0;
        const float* hr0 = hs + rq * HS + kBase;
        const float* hr1 = hs + (rq + 8) * HS + kBase;
        const float* c0 = Bs + cq * HS + kBase;
        const float* c1 = Bs + (cq + 4) * HS + kBase;
        const float* c2 = Bs + (cq + 8) * HS + kBase;
        const float* c3 = Bs + (cq + 12) * HS + kBase;
#pragma unroll
        for (int k = 0; k < 64; k += 4) {
            ulonglong2 h0v = *(const ulonglong2*)(hr0 + k);
            ulonglong2 h1v = *(const ulonglong2*)(hr1 + k);
            ulonglong2 b0 = *(const ulonglong2*)(c0 + k);
            ulonglong2 b1 = *(const ulonglong2*)(c1 + k);
            ulonglong2 b2 = *(const ulonglong2*)(c2 + k);
            ulonglong2 b3 = *(const ulonglong2*)(c3 + k);
            fma2(a00, h0v.x, b0.x); fma2(a00, h0v.y, b0.y);
            fma2(a01, h0v.x, b1.x); fma2(a01, h0v.y, b1.y);
            fma2(a02, h0v.x, b2.x); fma2(a02, h0v.y, b2.y);
            fma2(a03, h0v.x, b3.x); fma2(a03, h0v.y, b3.y);
            fma2(a10, h1v.x, b0.x); fma2(a10, h1v.y, b0.y);
            fma2(a11, h1v.x, b1.x); fma2(a11, h1v.y, b1.y);
            fma2(a12, h1v.x, b2.x); fma2(a12, h1v.y, b2.y);
            fma2(a13, h1v.x, b3.x); fma2(a13, h1v.y, b3.y);
        }
        __syncthreads();   // all reads of red from prev step done; safe to overwrite

        unsigned long long* rw = red + w * 264;
        rw[(rq) * 16 + cq] = a00;       rw[(rq) * 16 + cq + 4] = a01;
        rw[(rq) * 16 + cq + 8] = a02;   rw[(rq) * 16 + cq + 12] = a03;
        rw[(rq + 8) * 16 + cq] = a10;     rw[(rq + 8) * 16 + cq + 4] = a11;
        rw[(rq + 8) * 16 + cq + 8] = a12; rw[(rq + 8) * 16 + cq + 12] = a13;
        __syncthreads();

        {
            unsigned long long s = red[tid];
#pragma unroll
            for (int ww = 1; ww < 8; ++ww) add2(s, s, red[ww * 264 + tid]);
            float2 p = u2f(s);
            float z = p.x + p.y + xv;
            float a = fabsf(z) + bia;
            float r = (a > 0.f) ? copysignf(a, z) : 0.f;
            __stcg(out + (size_t)t * SLAB + (rowBase + orow) * 512 + n0 + ocol, r);
        }
        __threadfence();
        __syncthreads();   // all stores fenced before publishing
        if (tid == 0) {
            asm volatile("st.global.cg.u32 [%0], %1;"
                         :: "l"(&g_flag[myflag]), "r"((unsigned int)(t + 1)));
        }
    }
}

extern "C" void kernel_launch(void* const* d_in, const int* in_sizes, int n_in,
                              void* d_out, int out_size) {
    const float* x    = (const float*)d_in[0];
    const float* T    = (const float*)d_in[1];
    const float* B    = (const float*)d_in[2];
    const float* bias = (const float*)d_in[3];
    const float* h0   = (const float*)d_in[4];
    float* out = (float*)d_out;

    dim3 g1(512, 16);
    p1<<<g1, 128>>>(x, T, out);

    size_t smem2 = (size_t)(32 * HS) * sizeof(float) + (size_t)(8 * 264) * sizeof(unsigned long long);
    cudaFuncSetAttribute(p2, cudaFuncAttributeMaxDynamicSharedMemorySize, (int)smem2);
    dim3 g2(32, 4);
    p2<<<g2, 256, smem2>>>(out, B, bias, h0);
}

// round 9
// speedup vs baseline: 2.2926x; 2.2926x over previous
#include <cuda_runtime.h>
#include <cuda_bf16.h>

#define SLAB 32768          // 64*512 floats per time slab
#define HS 516              // padded stride (conflict-free LDS.128)
#define RSTRIDE 17          // red row stride (ulonglong), conflict-free
#define RWARP (16 * RSTRIDE)

__device__ unsigned int g_flag[1024];   // 128 flags padded to 32B each

__device__ __forceinline__ void fma2(unsigned long long& d, unsigned long long a, unsigned long long b) {
    asm("fma.rn.f32x2 %0, %1, %2, %0;" : "+l"(d) : "l"(a), "l"(b));
}
__device__ __forceinline__ void add2(unsigned long long& d, unsigned long long a, unsigned long long b) {
    asm("add.rn.f32x2 %0, %1, %2;" : "=l"(d) : "l"(a), "l"(b));
}
__device__ __forceinline__ float2 u2f(unsigned long long v) {
    float2 r; asm("mov.b64 {%0, %1}, %2;" : "=f"(r.x), "=f"(r.y) : "l"(v)); return r;
}

// ---------------- Phase 1: out[t][b][u] = (x @ T)  ----------------
__global__ void __launch_bounds__(128) p1(const float* __restrict__ X,
                                          const float* __restrict__ T,
                                          float* __restrict__ out) {
    __shared__ float As[64 * 20];
    __shared__ float Ts[32 * 20];
    const int tid = threadIdx.x;
    if (blockIdx.x == 0 && blockIdx.y == 0 && tid < 128) {
        g_flag[tid * 8] = 0u;
    }

    const int rowBase = blockIdx.x * 64;
    const int n0 = blockIdx.y * 32;
    const int mq = tid >> 3;
    const int nq = tid & 7;

    unsigned long long acc[4][4];
#pragma unroll
    for (int i = 0; i < 4; ++i)
#pragma unroll
        for (int j = 0; j < 4; ++j) acc[i][j] = 0ull;

    for (int kb = 0; kb < 256; kb += 16) {
#pragma unroll
        for (int i2 = 0; i2 < 2; ++i2) {
            int q = tid + i2 * 128;
            int m = q >> 2, kq = (q & 3) * 4;
            *(float4*)&As[m * 20 + kq] = *(const float4*)&X[(rowBase + m) * 256 + kb + kq];
        }
        {
            int k = tid >> 3, n4 = (tid & 7) * 4;
            float4 v = *(const float4*)&T[(kb + k) * 512 + n0 + n4];
            Ts[(n4 + 0) * 20 + k] = v.x;
            Ts[(n4 + 1) * 20 + k] = v.y;
            Ts[(n4 + 2) * 20 + k] = v.z;
            Ts[(n4 + 3) * 20 + k] = v.w;
        }
        __syncthreads();
#pragma unroll
        for (int k = 0; k < 16; k += 4) {
            ulonglong2 a0 = *(const ulonglong2*)&As[(mq) * 20 + k];
            ulonglong2 a1 = *(const ulonglong2*)&As[(mq + 16) * 20 + k];
            ulonglong2 a2 = *(const ulonglong2*)&As[(mq + 32) * 20 + k];
            ulonglong2 a3 = *(const ulonglong2*)&As[(mq + 48) * 20 + k];
            ulonglong2 b0 = *(const ulonglong2*)&Ts[(nq) * 20 + k];
            ulonglong2 b1 = *(const ulonglong2*)&Ts[(nq + 8) * 20 + k];
            ulonglong2 b2 = *(const ulonglong2*)&Ts[(nq + 16) * 20 + k];
            ulonglong2 b3 = *(const ulonglong2*)&Ts[(nq + 24) * 20 + k];
            fma2(acc[0][0], a0.x, b0.x); fma2(acc[0][0], a0.y, b0.y);
            fma2(acc[0][1], a0.x, b1.x); fma2(acc[0][1], a0.y, b1.y);
            fma2(acc[0][2], a0.x, b2.x); fma2(acc[0][2], a0.y, b2.y);
            fma2(acc[0][3], a0.x, b3.x); fma2(acc[0][3], a0.y, b3.y);
            fma2(acc[1][0], a1.x, b0.x); fma2(acc[1][0], a1.y, b0.y);
            fma2(acc[1][1], a1.x, b1.x); fma2(acc[1][1], a1.y, b1.y);
            fma2(acc[1][2], a1.x, b2.x); fma2(acc[1][2], a1.y, b2.y);
            fma2(acc[1][3], a1.x, b3.x); fma2(acc[1][3], a1.y, b3.y);
            fma2(acc[2][0], a2.x, b0.x); fma2(acc[2][0], a2.y, b0.y);
            fma2(acc[2][1], a2.x, b1.x); fma2(acc[2][1], a2.y, b1.y);
            fma2(acc[2][2], a2.x, b2.x); fma2(acc[2][2], a2.y, b2.y);
            fma2(acc[2][3], a2.x, b3.x); fma2(acc[2][3], a2.y, b3.y);
            fma2(acc[3][0], a3.x, b0.x); fma2(acc[3][0], a3.y, b0.y);
            fma2(acc[3][1], a3.x, b1.x); fma2(acc[3][1], a3.y, b1.y);
            fma2(acc[3][2], a3.x, b2.x); fma2(acc[3][2], a3.y, b2.y);
            fma2(acc[3][3], a3.x, b3.x); fma2(acc[3][3], a3.y, b3.y);
        }
        __syncthreads();
    }
#pragma unroll
    for (int i = 0; i < 4; ++i) {
        int r = rowBase + mq + 16 * i;
        int tt = r & 511, bb = r >> 9;
        float* p = out + tt * SLAB + bb * 512 + n0 + nq;
#pragma unroll
        for (int j = 0; j < 4; ++j) {
            float2 v = u2f(acc[i][j]);
            p[8 * j] = v.x + v.y;
        }
    }
}

// ---------------- Phase 2: recurrence, persistent 128 blocks ----------------
// grid (32,4): bx = utile (16 cols), g = group (16 rows). 256 thr = 8 warps.
// Sync: per-block padded flag; warp 0's 32 lanes poll the group's 32 producer
// flags in parallel with ld.acquire.gpu + nanosleep backoff; block barrier
// releases the rest. Publish via st.release.gpu after fence+barrier.
__global__ void __launch_bounds__(256) p2(float* __restrict__ out,
                                          const float* __restrict__ B,
                                          const float* __restrict__ bias,
                                          const float* __restrict__ h0) {
    extern __shared__ float sm[];
    float* Bs = sm;                                              // 16 x HS
    float* hs = sm + 16 * HS;                                    // 16 x HS
    unsigned long long* red = (unsigned long long*)(sm + 32 * HS);  // 8 x RWARP

    const int tid = threadIdx.x;
    const int w = tid >> 5, lane = tid & 31;
    const int rq = lane & 7, cq = lane >> 3;
    const int g = blockIdx.y, bx = blockIdx.x;
    const int n0 = bx * 16, rowBase = g * 16;
    const int kBase = w * 64;
    const int orow = tid >> 4, ocol = tid & 15;
    const float bia = bias[n0 + ocol];
    unsigned int* const myflag = &g_flag[(g * 32 + bx) * 8];
    const unsigned int* const pollflag = &g_flag[(g * 32 + lane) * 8];
    float* const outbase = out + (size_t)(rowBase + orow) * 512 + n0 + ocol;

    // one-time B slab (transposed): Bs[c][k] = B[k][n0+c]
    for (int idx = tid; idx < 16 * 512; idx += 256) {
        int k = idx >> 4, c = idx & 15;
        Bs[c * HS + k] = B[k * 512 + n0 + c];
    }
    __syncthreads();

    for (int t = 0; t < 512; ++t) {
        // prefetch xT term (L2 latency hides under the poll)
        float xv = __ldcg(outbase + (size_t)t * SLAB);

        if (t > 0) {
            if (w == 0) {   // single polling warp; 32 lanes watch 32 producers
                for (;;) {
                    unsigned int v;
                    asm volatile("ld.acquire.gpu.global.u32 %0, [%1];"
                                 : "=r"(v) : "l"(pollflag) : "memory");
                    if (__all_sync(0xffffffffu, v >= (unsigned int)t)) break;
                    __nanosleep(64);
                }
            }
        }
        __syncthreads();   // bar1: release warps; also guards red reuse

        if (t > 0) {
            const float* hsrc = out + (size_t)(t - 1) * SLAB + rowBase * 512 + kBase;
#pragma unroll
            for (int i = 0; i < 8; ++i) {
                int u = lane + 32 * i;
                int r = u >> 4, c4 = (u & 15) * 4;
                float4 v = __ldcg((const float4*)(hsrc + r * 512 + c4));
                *(float4*)&hs[r * HS + kBase + c4] = v;
            }
        } else {
#pragma unroll
            for (int i = 0; i < 8; ++i) {
                int u = lane + 32 * i;
                int r = u >> 4, c4 = (u & 15) * 4;
                *(float4*)&hs[r * HS + kBase + c4] = *(const float4*)(h0 + kBase + c4);
            }
        }
        __syncwarp();

        unsigned long long a00 = 0, a01 = 0, a02 = 0, a03 = 0;
        unsigned long long a10 = 0, a11 = 0, a12 = 0, a13 = 0;
        const float* hr0 = hs + rq * HS + kBase;
        const float* hr1 = hs + (rq + 8) * HS + kBase;
        const float* c0 = Bs + cq * HS + kBase;
        const float* c1 = Bs + (cq + 4) * HS + kBase;
        const float* c2 = Bs + (cq + 8) * HS + kBase;
        const float* c3 = Bs + (cq + 12) * HS + kBase;
#pragma unroll
        for (int k = 0; k < 64; k += 4) {
            ulonglong2 h0v = *(const ulonglong2*)(hr0 + k);
            ulonglong2 h1v = *(const ulonglong2*)(hr1 + k);
            ulonglong2 b0 = *(const ulonglong2*)(c0 + k);
            ulonglong2 b1 = *(const ulonglong2*)(c1 + k);
            ulonglong2 b2 = *(const ulonglong2*)(c2 + k);
            ulonglong2 b3 = *(const ulonglong2*)(c3 + k);
            fma2(a00, h0v.x, b0.x); fma2(a00, h0v.y, b0.y);
            fma2(a01, h0v.x, b1.x); fma2(a01, h0v.y, b1.y);
            fma2(a02, h0v.x, b2.x); fma2(a02, h0v.y, b2.y);
            fma2(a03, h0v.x, b3.x); fma2(a03, h0v.y, b3.y);
            fma2(a10, h1v.x, b0.x); fma2(a10, h1v.y, b0.y);
            fma2(a11, h1v.x, b1.x); fma2(a11, h1v.y, b1.y);
            fma2(a12, h1v.x, b2.x); fma2(a12, h1v.y, b2.y);
            fma2(a13, h1v.x, b3.x); fma2(a13, h1v.y, b3.y);
        }

        unsigned long long* rw = red + w * RWARP;
        rw[(rq) * RSTRIDE + cq] = a00;       rw[(rq) * RSTRIDE + cq + 4] = a01;
        rw[(rq) * RSTRIDE + cq + 8] = a02;   rw[(rq) * RSTRIDE + cq + 12] = a03;
        rw[(rq + 8) * RSTRIDE + cq] = a10;     rw[(rq + 8) * RSTRIDE + cq + 4] = a11;
        rw[(rq + 8) * RSTRIDE + cq + 8] = a12; rw[(rq + 8) * RSTRIDE + cq + 12] = a13;
        __syncthreads();   // bar2: partials visible

        {
            int base = orow * RSTRIDE + ocol;
            unsigned long long s = red[base];
#pragma unroll
            for (int ww = 1; ww < 8; ++ww) add2(s, s, red[ww * RWARP + base]);
            float2 p = u2f(s);
            float z = p.x + p.y + xv;
            float a = fabsf(z) + bia;
            float r = (a > 0.f) ? copysignf(a, z) : 0.f;
            __stcg(outbase + (size_t)t * SLAB, r);
        }
        __threadfence();   // make h stores gpu-visible
        __syncthreads();   // bar3: all threads stored+fenced
        if (tid == 0) {
            asm volatile("st.release.gpu.global.u32 [%0], %1;"
                         :: "l"(myflag), "r"((unsigned int)(t + 1)) : "memory");
        }
    }
}

extern "C" void kernel_launch(void* const* d_in, const int* in_sizes, int n_in,
                              void* d_out, int out_size) {
    const float* x    = (const float*)d_in[0];
    const float* T    = (const float*)d_in[1];
    const float* B    = (const float*)d_in[2];
    const float* bias = (const float*)d_in[3];
    const float* h0   = (const float*)d_in[4];
    float* out = (float*)d_out;

    dim3 g1(512, 16);
    p1<<<g1, 128>>>(x, T, out);

    size_t smem2 = (size_t)(32 * HS) * sizeof(float)
                 + (size_t)(8 * RWARP) * sizeof(unsigned long long);   // 83456 B
    cudaFuncSetAttribute(p2, cudaFuncAttributeMaxDynamicSharedMemorySize, (int)smem2);
    dim3 g2(32, 4);
    p2<<<g2, 256, smem2>>>(out, B, bias, h0);
}

// round 11
// speedup vs baseline: 2.3457x; 1.0232x over previous
#include <cuda_runtime.h>
#include <cuda_bf16.h>

#define SLAB 32768          // 64*512 floats per time slab
#define HS 516              // padded stride (conflict-free LDS.128)
#define RSTRIDE 17          // red row stride (ulonglong)
#define RW8 (8 * RSTRIDE)   // per-warp red region (8 rows x 16 cols padded)

__device__ unsigned int g_flag[2048];   // 256 flags padded to 32B each

__device__ __forceinline__ void fma2(unsigned long long& d, unsigned long long a, unsigned long long b) {
    asm("fma.rn.f32x2 %0, %1, %2, %0;" : "+l"(d) : "l"(a), "l"(b));
}
__device__ __forceinline__ void add2(unsigned long long& d, unsigned long long a, unsigned long long b) {
    asm("add.rn.f32x2 %0, %1, %2;" : "=l"(d) : "l"(a), "l"(b));
}
__device__ __forceinline__ float2 u2f(unsigned long long v) {
    float2 r; asm("mov.b64 {%0, %1}, %2;" : "=f"(r.x), "=f"(r.y) : "l"(v)); return r;
}

// ---------------- Phase 1: out[t][b][u] = (x @ T)  ----------------
__global__ void __launch_bounds__(128) p1(const float* __restrict__ X,
                                          const float* __restrict__ T,
                                          float* __restrict__ out) {
    __shared__ float As[64 * 20];
    __shared__ float Ts[32 * 20];
    const int tid = threadIdx.x;
    if (blockIdx.x == 0 && blockIdx.y == 0) {
        g_flag[tid * 8] = 0u;
        g_flag[(tid + 128) * 8] = 0u;
    }

    const int rowBase = blockIdx.x * 64;
    const int n0 = blockIdx.y * 32;
    const int mq = tid >> 3;
    const int nq = tid & 7;

    unsigned long long acc[4][4];
#pragma unroll
    for (int i = 0; i < 4; ++i)
#pragma unroll
        for (int j = 0; j < 4; ++j) acc[i][j] = 0ull;

    for (int kb = 0; kb < 256; kb += 16) {
#pragma unroll
        for (int i2 = 0; i2 < 2; ++i2) {
            int q = tid + i2 * 128;
            int m = q >> 2, kq = (q & 3) * 4;
            *(float4*)&As[m * 20 + kq] = *(const float4*)&X[(rowBase + m) * 256 + kb + kq];
        }
        {
            int k = tid >> 3, n4 = (tid & 7) * 4;
            float4 v = *(const float4*)&T[(kb + k) * 512 + n0 + n4];
            Ts[(n4 + 0) * 20 + k] = v.x;
            Ts[(n4 + 1) * 20 + k] = v.y;
            Ts[(n4 + 2) * 20 + k] = v.z;
            Ts[(n4 + 3) * 20 + k] = v.w;
        }
        __syncthreads();
#pragma unroll
        for (int k = 0; k < 16; k += 4) {
            ulonglong2 a0 = *(const ulonglong2*)&As[(mq) * 20 + k];
            ulonglong2 a1 = *(const ulonglong2*)&As[(mq + 16) * 20 + k];
            ulonglong2 a2 = *(const ulonglong2*)&As[(mq + 32) * 20 + k];
            ulonglong2 a3 = *(const ulonglong2*)&As[(mq + 48) * 20 + k];
            ulonglong2 b0 = *(const ulonglong2*)&Ts[(nq) * 20 + k];
            ulonglong2 b1 = *(const ulonglong2*)&Ts[(nq + 8) * 20 + k];
            ulonglong2 b2 = *(const ulonglong2*)&Ts[(nq + 16) * 20 + k];
            ulonglong2 b3 = *(const ulonglong2*)&Ts[(nq + 24) * 20 + k];
            fma2(acc[0][0], a0.x, b0.x); fma2(acc[0][0], a0.y, b0.y);
            fma2(acc[0][1], a0.x, b1.x); fma2(acc[0][1], a0.y, b1.y);
            fma2(acc[0][2], a0.x, b2.x); fma2(acc[0][2], a0.y, b2.y);
            fma2(acc[0][3], a0.x, b3.x); fma2(acc[0][3], a0.y, b3.y);
            fma2(acc[1][0], a1.x, b0.x); fma2(acc[1][0], a1.y, b0.y);
            fma2(acc[1][1], a1.x, b1.x); fma2(acc[1][1], a1.y, b1.y);
            fma2(acc[1][2], a1.x, b2.x); fma2(acc[1][2], a1.y, b2.y);
            fma2(acc[1][3], a1.x, b3.x); fma2(acc[1][3], a1.y, b3.y);
            fma2(acc[2][0], a2.x, b0.x); fma2(acc[2][0], a2.y, b0.y);
            fma2(acc[2][1], a2.x, b1.x); fma2(acc[2][1], a2.y, b1.y);
            fma2(acc[2][2], a2.x, b2.x); fma2(acc[2][2], a2.y, b2.y);
            fma2(acc[2][3], a2.x, b3.x); fma2(acc[2][3], a2.y, b3.y);
            fma2(acc[3][0], a3.x, b0.x); fma2(acc[3][0], a3.y, b0.y);
            fma2(acc[3][1], a3.x, b1.x); fma2(acc[3][1], a3.y, b1.y);
            fma2(acc[3][2], a3.x, b2.x); fma2(acc[3][2], a3.y, b2.y);
            fma2(acc[3][3], a3.x, b3.x); fma2(acc[3][3], a3.y, b3.y);
        }
        __syncthreads();
    }
#pragma unroll
    for (int i = 0; i < 4; ++i) {
        int r = rowBase + mq + 16 * i;
        int tt = r & 511, bb = r >> 9;
        float* p = out + tt * SLAB + bb * 512 + n0 + nq;
#pragma unroll
        for (int j = 0; j < 4; ++j) {
            float2 v = u2f(acc[i][j]);
            p[8 * j] = v.x + v.y;
        }
    }
}

// ---------------- Phase 2: dual-chain recurrence, persistent 128 blocks ----
// 8 groups x 8 batch rows; 32 utiles x 16 cols. Block (bx, j) interleaves two
// independent chains: group 2j (rows 16j..16j+8) and group 2j+1 (rows +8..+16).
// Each chain uses the R5-proven flag protocol; B-phase compute hides A's flag
// round-trip and vice versa.
struct ChainCtx {
    float* hs;                       // 8 x HS smem tile
    const unsigned int* pollflag;    // this lane's producer flag
    unsigned int* myflag;
    int rowBase;
    float* outRC;                    // out + (rowBase+orow)*512 + n0 + ocol
};

__device__ __forceinline__ void chain_step(
    int t, const ChainCtx& C, const float* __restrict__ Bs,
    unsigned long long* __restrict__ red,
    float* __restrict__ out, const float* __restrict__ h0,
    float bia, int tid, int w, int lane, int rq, int cq, int kBase)
{
    // prefetch xT term (hides under poll/compute)
    float xv = __ldcg(C.outRC + (size_t)t * SLAB);

    if (t > 0) {
        if (w == 0) {   // single polling warp: 32 lanes watch 32 producers
            for (;;) {
                unsigned int v;
                asm volatile("ld.acquire.gpu.global.u32 %0, [%1];"
                             : "=r"(v) : "l"(C.pollflag) : "memory");
                if (__all_sync(0xffffffffu, v >= (unsigned int)t)) break;
                __nanosleep(32);
            }
        }
    }
    __syncthreads();   // bar1: release warps; also separates red/hs reuse

    // stage this warp's h slice: 8 rows x 64 cols
    if (t > 0) {
        const float* hsrc = out + (size_t)(t - 1) * SLAB + C.rowBase * 512 + kBase;
#pragma unroll
        for (int i = 0; i < 4; ++i) {
            int u = lane + 32 * i;
            int r = u >> 4, c4 = (u & 15) * 4;
            float4 v = __ldcg((const float4*)(hsrc + r * 512 + c4));
            *(float4*)&C.hs[r * HS + kBase + c4] = v;
        }
    } else {
#pragma unroll
        for (int i = 0; i < 4; ++i) {
            int u = lane + 32 * i;
            int r = u >> 4, c4 = (u & 15) * 4;
            *(float4*)&C.hs[r * HS + kBase + c4] = *(const float4*)(h0 + kBase + c4);
        }
    }
    __syncwarp();

    // compute: lane -> row rq, cols {cq, cq+4, cq+8, cq+12}, k-slice [kBase, kBase+64)
    unsigned long long a0 = 0, a1 = 0, a2 = 0, a3 = 0;
    const float* hr = C.hs + rq * HS + kBase;
    const float* c0 = Bs + cq * HS + kBase;
    const float* c1 = c0 + 4 * HS;
    const float* c2 = c0 + 8 * HS;
    const float* c3 = c0 + 12 * HS;
#pragma unroll
    for (int k = 0; k < 64; k += 4) {
        ulonglong2 hv = *(const ulonglong2*)(hr + k);
        ulonglong2 b0 = *(const ulonglong2*)(c0 + k);
        ulonglong2 b1 = *(const ulonglong2*)(c1 + k);
        ulonglong2 b2 = *(const ulonglong2*)(c2 + k);
        ulonglong2 b3 = *(const ulonglong2*)(c3 + k);
        fma2(a0, hv.x, b0.x); fma2(a0, hv.y, b0.y);
        fma2(a1, hv.x, b1.x); fma2(a1, hv.y, b1.y);
        fma2(a2, hv.x, b2.x); fma2(a2, hv.y, b2.y);
        fma2(a3, hv.x, b3.x); fma2(a3, hv.y, b3.y);
    }

    unsigned long long* rw = red + w * RW8;
    rw[rq * RSTRIDE + cq]      = a0;
    rw[rq * RSTRIDE + cq + 4]  = a1;
    rw[rq * RSTRIDE + cq + 8]  = a2;
    rw[rq * RSTRIDE + cq + 12] = a3;
    __syncthreads();   // bar2: partials visible

    if (tid < 128) {   // 8 rows x 16 cols = 128 outputs
        int base = (tid >> 4) * RSTRIDE + (tid & 15);
        unsigned long long s = red[base];
#pragma unroll
        for (int ww = 1; ww < 8; ++ww) add2(s, s, red[ww * RW8 + base]);
        float2 p = u2f(s);
        float z = p.x + p.y + xv;
        float a = fabsf(z) + bia;
        float r = (a > 0.f) ? copysignf(a, z) : 0.f;
        __stcg(C.outRC + (size_t)t * SLAB, r);
    }
    __syncthreads();   // bar3: all stores done (happens-before tid0's release)
    if (tid == 0) {
        asm volatile("st.release.gpu.global.u32 [%0], %1;"
                     :: "l"(C.myflag), "r"((unsigned int)(t + 1)) : "memory");
    }
}

__global__ void __launch_bounds__(256) p2(float* __restrict__ out,
                                          const float* __restrict__ B,
                                          const float* __restrict__ bias,
                                          const float* __restrict__ h0) {
    extern __shared__ float sm[];
    float* Bs  = sm;                    // 16 x HS
    float* hsA = sm + 16 * HS;          // 8 x HS
    float* hsB = hsA + 8 * HS;          // 8 x HS
    unsigned long long* red = (unsigned long long*)(sm + 32 * HS);  // 8 x RW8

    const int tid = threadIdx.x;
    const int w = tid >> 5, lane = tid & 31;
    const int rq = lane & 7, cq = lane >> 3;
    const int bx = blockIdx.x, j = blockIdx.y;
    const int n0 = bx * 16;
    const int kBase = w * 64;
    const int orow = tid >> 4, ocol = tid & 15;   // orow 0..15; only tid<128 stores
    const float bia = bias[n0 + ocol];
    const int gA = 2 * j, gB = 2 * j + 1;

    ChainCtx A, Bc;
    A.hs = hsA;  A.rowBase = 16 * j;
    Bc.hs = hsB; Bc.rowBase = 16 * j + 8;
    A.myflag  = &g_flag[(gA * 32 + bx) * 8];
    Bc.myflag = &g_flag[(gB * 32 + bx) * 8];
    A.pollflag  = &g_flag[(gA * 32 + lane) * 8];
    Bc.pollflag = &g_flag[(gB * 32 + lane) * 8];
    A.outRC  = out + (size_t)(A.rowBase  + (orow & 7)) * 512 + n0 + ocol;
    Bc.outRC = out + (size_t)(Bc.rowBase + (orow & 7)) * 512 + n0 + ocol;

    // one-time B slab (transposed): Bs[c][k] = B[k][n0+c]
    for (int idx = tid; idx < 16 * 512; idx += 256) {
        int k = idx >> 4, c = idx & 15;
        Bs[c * HS + k] = B[k * 512 + n0 + c];
    }
    __syncthreads();

    for (int t = 0; t < 512; ++t) {
        chain_step(t, A,  Bs, red, out, h0, bia, tid, w, lane, rq, cq, kBase);
        chain_step(t, Bc, Bs, red, out, h0, bia, tid, w, lane, rq, cq, kBase);
    }
}

extern "C" void kernel_launch(void* const* d_in, const int* in_sizes, int n_in,
                              void* d_out, int out_size) {
    const float* x    = (const float*)d_in[0];
    const float* T    = (const float*)d_in[1];
    const float* B    = (const float*)d_in[2];
    const float* bias = (const float*)d_in[3];
    const float* h0   = (const float*)d_in[4];
    float* out = (float*)d_out;

    dim3 g1(512, 16);
    p1<<<g1, 128>>>(x, T, out);

    size_t smem2 = (size_t)(32 * HS) * sizeof(float)
                 + (size_t)(8 * RW8) * sizeof(unsigned long long);   // 74.8 KB
    cudaFuncSetAttribute(p2, cudaFuncAttributeMaxDynamicSharedMemorySize, (int)smem2);
    dim3 g2(32, 4);
    p2<<<g2, 256, smem2>>>(out, B, bias, h0);
}